// round 15
// baseline (speedup 1.0000x reference)
#include <cuda_runtime.h>
#include <cstdint>

// Circuit in linear probability space (one log at the end):
//   p_v = exp(l_v);  s = p1(1-p2) + (1-p1)p2;  t = p1*p2
//   out = log(p0*s + (1-p0)*t)
// Identical to the reference's nested logsumexp (slot-9's -1000 disjunct
// exp-underflows to exactly 0 there too).
__device__ __forceinline__ float circuit_eval(float l0, float l1, float l2) {
    float p0 = __expf(l0);
    float p1 = __expf(l1);
    float p2 = __expf(l2);

    float t  = p1 * p2;
    float a  = __fmaf_rn(-p1, p2, p1);    // p1*(1-p2)
    float b  = __fmaf_rn(-p1, p2, p2);    // (1-p1)*p2
    float s  = a + b;

    float q0 = 1.0f - p0;
    float x  = __fmaf_rn(p0, s, q0 * t);
    return __logf(x);
}

// Best-measured configuration (R11, 10.72us): CTA-wide cp.async pipeline.
//   THREADS=128, tile = 512 elements (384 float4 in = 3 cp.async/thread,
//   128 float4 out = 1 store/thread), 4 stages x 6.15KB = 24.6KB smem
//   -> 8 CTAs/SM, grid 1184 = one exact wave, 98.8% tile balance.
// Delta vs R11: refill is issued immediately after the stage's smem reads
// complete (before compute+store), starting each tile's memory earlier.
static constexpr int THREADS        = 128;
static constexpr int ELEMS_PER_TILE = 512;
static constexpr int F4_PER_TILE    = 384;   // 512 elems * 3 floats / 4
static constexpr int STAGES         = 4;

__global__ void __launch_bounds__(THREADS)
circuit_kernel(const float4* __restrict__ in, float4* __restrict__ out,
               int n_tiles) {
    __shared__ __align__(16) float4 buf[STAGES][F4_PER_TILE];

    const int t      = threadIdx.x;
    const int stride = gridDim.x;

    // Issue one tile's loads into a stage (3 x 16B cp.async per thread,
    // each instruction coalesced across the warp), then commit the group.
    // Out-of-range tiles commit an empty group to keep group counts uniform.
    auto issue = [&](int tile, int stage) {
        if (tile < n_tiles) {
            const float4* src = in + (size_t)tile * F4_PER_TILE;
            uint32_t dst = (uint32_t)__cvta_generic_to_shared(&buf[stage][0]);
#pragma unroll
            for (int k = 0; k < 3; k++) {
                asm volatile(
                    "cp.async.cg.shared.global [%0], [%1], 16;"
                    :: "r"(dst + (uint32_t)((k * THREADS + t) * 16)),
                       "l"(src + k * THREADS + t));
            }
        }
        asm volatile("cp.async.commit_group;");
    };

    // Prologue: fill the pipeline.
#pragma unroll
    for (int s = 0; s < STAGES; s++)
        issue(blockIdx.x + s * stride, s);

    int stage = 0;
    int ahead = blockIdx.x + STAGES * stride;
    for (int i = blockIdx.x; i < n_tiles; i += stride) {
        // Oldest outstanding group (tile i) has landed; make all threads'
        // copies visible to each other.
        asm volatile("cp.async.wait_group %0;" :: "n"(STAGES - 1));
        __syncthreads();

        // Thread t owns elements 4t..4t+3 = float4s 3t..3t+2 of the tile.
        // 48B lane stride -> banks {12l..12l+3 mod 32}: conflict-free LDS.128.
        float4 a = buf[stage][3 * t + 0];
        float4 b = buf[stage][3 * t + 1];
        float4 c = buf[stage][3 * t + 2];

        // All threads' reads of this stage are done -> refill it NOW, so the
        // next tile's memory overlaps this tile's compute AND store.
        __syncthreads();
        issue(ahead, stage);
        ahead += stride;

        float4 r;
        r.x = circuit_eval(a.x, a.y, a.z);
        r.y = circuit_eval(a.w, b.x, b.y);
        r.z = circuit_eval(b.z, b.w, c.x);
        r.w = circuit_eval(c.y, c.z, c.w);

        // Coalesced store (contiguous 512B per warp).
        out[(size_t)i * (ELEMS_PER_TILE / 4) + t] = r;

        stage = (stage + 1) & (STAGES - 1);
    }
}

// Tail for elements beyond the last full CTA tile (not hit for B=4194304).
__global__ void circuit_tail_kernel(const float* __restrict__ in,
                                    float* __restrict__ out,
                                    int start, int n) {
    int i = start + blockIdx.x * blockDim.x + threadIdx.x;
    if (i >= n) return;
    out[i] = circuit_eval(in[3 * i + 0], in[3 * i + 1], in[3 * i + 2]);
}

extern "C" void kernel_launch(void* const* d_in, const int* in_sizes, int n_in,
                              void* d_out, int out_size) {
    const float* log_probs = (const float*)d_in[0];
    float* out = (float*)d_out;

    int B = out_size;                    // output is (1, B) floats
    int n_tiles = B / ELEMS_PER_TILE;    // 512 elements per CTA tile

    if (n_tiles > 0) {
        // One exact wave: 148 SMs x 8 CTAs (24.6KB smem, 128 thr each).
        int blocks = 8 * 148;
        if (blocks > n_tiles) blocks = n_tiles;
        circuit_kernel<<<blocks, THREADS>>>(
            (const float4*)log_probs, (float4*)out, n_tiles);
    }
    int done = n_tiles * ELEMS_PER_TILE;
    if (done < B) {
        int rem = B - done;
        circuit_tail_kernel<<<(rem + 255) / 256, 256>>>(log_probs, out, done, B);
    }
}

// round 16
// speedup vs baseline: 1.0239x; 1.0239x over previous
#include <cuda_runtime.h>
#include <cstdint>

// FINAL KERNEL — measured best (10.72us, ~6.25TB/s effective on 67MB).
//
// Circuit in linear probability space (one log at the end):
//   p_v = exp(l_v);  s = p1(1-p2) + (1-p1)p2;  t = p1*p2
//   out = log(p0*s + (1-p0)*t)
// Identical to the reference's nested logsumexp (slot-9's -1000 disjunct
// exp-underflows to exactly 0 there too). 3 MUFU.EX2 + 1 MUFU.LG2 + ~7 FMA
// per element; compute floor (~3.5us) fully hidden under memory.
__device__ __forceinline__ float circuit_eval(float l0, float l1, float l2) {
    float p0 = __expf(l0);
    float p1 = __expf(l1);
    float p2 = __expf(l2);

    float t  = p1 * p2;
    float a  = __fmaf_rn(-p1, p2, p1);    // p1*(1-p2)
    float b  = __fmaf_rn(-p1, p2, p2);    // (1-p1)*p2
    float s  = a + b;

    float q0 = 1.0f - p0;
    float x  = __fmaf_rn(p0, s, q0 * t);  // both terms positive: no cancellation
    return __logf(x);
}

// CTA-wide cp.async pipeline:
//   THREADS=128, tile = 512 elements (384 float4 in = 3 cp.async/thread,
//   128 float4 out = 1 store/thread), 4 stages x 6.15KB = 24.6KB smem
//   -> 8 CTAs/SM, grid 1184 = one exact wave,
//   8192 tiles / 1184 CTAs = 6.92 -> critical path 7 = 98.8% balance.
static constexpr int THREADS        = 128;
static constexpr int ELEMS_PER_TILE = 512;
static constexpr int F4_PER_TILE    = 384;   // 512 elems * 3 floats / 4
static constexpr int STAGES         = 4;

__global__ void __launch_bounds__(THREADS)
circuit_kernel(const float4* __restrict__ in, float4* __restrict__ out,
               int n_tiles) {
    __shared__ __align__(16) float4 buf[STAGES][F4_PER_TILE];

    const int t      = threadIdx.x;
    const int stride = gridDim.x;

    // Issue one tile's loads into a stage (3 x 16B cp.async per thread,
    // each instruction coalesced across the warp), then commit the group.
    // Out-of-range tiles commit an empty group to keep group counts uniform.
    auto issue = [&](int tile, int stage) {
        if (tile < n_tiles) {
            const float4* src = in + (size_t)tile * F4_PER_TILE;
            uint32_t dst = (uint32_t)__cvta_generic_to_shared(&buf[stage][0]);
#pragma unroll
            for (int k = 0; k < 3; k++) {
                asm volatile(
                    "cp.async.cg.shared.global [%0], [%1], 16;"
                    :: "r"(dst + (uint32_t)((k * THREADS + t) * 16)),
                       "l"(src + k * THREADS + t));
            }
        }
        asm volatile("cp.async.commit_group;");
    };

    // Prologue: fill the pipeline (3 tiles in flight while computing one).
#pragma unroll
    for (int s = 0; s < STAGES; s++)
        issue(blockIdx.x + s * stride, s);

    int stage = 0;
    int ahead = blockIdx.x + STAGES * stride;
    for (int i = blockIdx.x; i < n_tiles; i += stride) {
        // Oldest outstanding group (tile i) has landed; make all threads'
        // copies visible to each other.
        asm volatile("cp.async.wait_group %0;" :: "n"(STAGES - 1));
        __syncthreads();

        // Thread t owns elements 4t..4t+3 = float4s 3t..3t+2 of the tile.
        // 48B lane stride -> banks {12l..12l+3 mod 32}: conflict-free LDS.128.
        float4 a = buf[stage][3 * t + 0];
        float4 b = buf[stage][3 * t + 1];
        float4 c = buf[stage][3 * t + 2];

        float4 r;
        r.x = circuit_eval(a.x, a.y, a.z);
        r.y = circuit_eval(a.w, b.x, b.y);
        r.z = circuit_eval(b.z, b.w, c.x);
        r.w = circuit_eval(c.y, c.z, c.w);

        // Coalesced store (contiguous 512B per warp).
        out[(size_t)i * (ELEMS_PER_TILE / 4) + t] = r;

        // All threads done reading this stage before it is refilled.
        __syncthreads();
        issue(ahead, stage);
        ahead += stride;
        stage = (stage + 1) & (STAGES - 1);
    }
}

// Tail for elements beyond the last full CTA tile (not hit for B=4194304).
__global__ void circuit_tail_kernel(const float* __restrict__ in,
                                    float* __restrict__ out,
                                    int start, int n) {
    int i = start + blockIdx.x * blockDim.x + threadIdx.x;
    if (i >= n) return;
    out[i] = circuit_eval(in[3 * i + 0], in[3 * i + 1], in[3 * i + 2]);
}

extern "C" void kernel_launch(void* const* d_in, const int* in_sizes, int n_in,
                              void* d_out, int out_size) {
    const float* log_probs = (const float*)d_in[0];
    float* out = (float*)d_out;

    int B = out_size;                    // output is (1, B) floats
    int n_tiles = B / ELEMS_PER_TILE;    // 512 elements per CTA tile

    if (n_tiles > 0) {
        // One exact wave: 148 SMs x 8 CTAs (24.6KB smem, 128 thr each).
        int blocks = 8 * 148;
        if (blocks > n_tiles) blocks = n_tiles;
        circuit_kernel<<<blocks, THREADS>>>(
            (const float4*)log_probs, (float4*)out, n_tiles);
    }
    int done = n_tiles * ELEMS_PER_TILE;
    if (done < B) {
        int rem = B - done;
        circuit_tail_kernel<<<(rem + 255) / 256, 256>>>(log_probs, out, done, B);
    }
}